// round 10
// baseline (speedup 1.0000x reference)
#include <cuda_runtime.h>
#include <cuda_bf16.h>

// ============================================================================
// Sinkhorn, N=8, P=2048, EPS=0.1, 50 iters.
//   a = (mu+1e-8)/(K b),  b = (nu+1e-8)/(K^T a),  b0 = 1,  K = exp(-C/eps)
// K stored as bf16 pairs (67MB, L2-resident). bf16->fp32 expansion is pure
// ALU (shift / mask), bypassing the quarter-rate F2F conversion pipe that
// bound the previous fp16 version (67M F2F/iter ~= 14us/iter, measured).
// ONE persistent kernel, per-batch software barriers. Each thread owns 8
// fixed columns; per 8-row band K lives in 8 uint4 registers reused by both
// the row-GEMV (pass1) and the column partials (pass2). K traverses L2 once
// per iteration. Deterministic (fixed reduction order, no float atomics).
//
// Output (fp32): [ cost(8) | pi(8*2048*2048) | C(8*2048*2048) ],
// pi recomputed from ORIGINAL fp32 C: pi = exp(ln a_i + ln b_j - 10*C_ij).
// ============================================================================

#define N_B   8
#define P     2048
#define NITER 50
#define RB    8                 // rows per band
#define NBANDS (P / RB)         // 256 bands per batch
#define TPB   256
#define MAXBB 64                // max blocks per batch (partials bound)
#define INV_EPS 10.0f

// scratch (static __device__ arrays: the sanctioned scratch mechanism)
static __device__ unsigned  K2[(size_t)N_B * P * (P / 2)];    // 67 MB bf16x2
static __device__ float     partials[(size_t)N_B * MAXBB * P]; // 4 MB
static __device__ float     b_buf[N_B * P];
static __device__ float     a_buf[N_B * P];
static __device__ float     cost_part[N_B * 128];

// per-batch software barriers (zero-init; ctr returns to 0, gen monotonic)
static __device__ unsigned bbar_ctr[N_B];
static __device__ volatile unsigned bbar_gen[N_B];

__device__ __forceinline__ void batch_sync(int n, int Bb) {
    __syncthreads();
    if (threadIdx.x == 0) {
        __threadfence();
        unsigned gen = bbar_gen[n];
        if (atomicAdd(&bbar_ctr[n], 1u) == (unsigned)(Bb - 1)) {
            bbar_ctr[n] = 0;
            __threadfence();
            bbar_gen[n] = gen + 1;
        } else {
            while (bbar_gen[n] == gen) { }
            __threadfence();
        }
    }
    __syncthreads();
}

// bf16-pair -> two floats, pure ALU (no F2F)
__device__ __forceinline__ float blo(unsigned u) { return __uint_as_float(u << 16); }
__device__ __forceinline__ float bhi(unsigned u) { return __uint_as_float(u & 0xFFFF0000u); }

// ---------------------------------------------------------------------------
// K = exp(-C/eps), fp32 -> bf16 pairs
__global__ __launch_bounds__(256) void k_prep(const float* __restrict__ C) {
    size_t i = (size_t)blockIdx.x * 256 + threadIdx.x;  // float4 idx, 8388608
    float4 c = __ldcs(reinterpret_cast<const float4*>(C) + i);
    __nv_bfloat162 h0 = __floats2bfloat162_rn(__expf(-INV_EPS * c.x),
                                              __expf(-INV_EPS * c.y));
    __nv_bfloat162 h1 = __floats2bfloat162_rn(__expf(-INV_EPS * c.z),
                                              __expf(-INV_EPS * c.w));
    K2[2 * i]     = *reinterpret_cast<unsigned*>(&h0);
    K2[2 * i + 1] = *reinterpret_cast<unsigned*>(&h1);
}

// ---------------------------------------------------------------------------
// Persistent iteration kernel. grid = G = 8*Bb blocks, 256 threads.
__global__ __launch_bounds__(TPB, 3) void k_main(const float* __restrict__ mu,
                                                 const float* __restrict__ nu,
                                                 int Bb) {
    __shared__ float wsum[RB * 8];   // [row][warp] partials
    __shared__ float ash[RB];        // a for current band

    int tid = threadIdx.x;
    int w   = tid >> 5;
    int l   = tid & 31;
    int n   = blockIdx.x / Bb;       // batch
    int r   = blockIdx.x % Bb;       // block index within batch

    // b0 = 1 (each batch inits its own slice)
    for (int e = r * TPB + tid; e < P; e += Bb * TPB)
        b_buf[n * P + e] = 1.0f;
    batch_sync(n, Bb);

    for (int it = 0; it < NITER; it++) {
        // this thread's 8 b-values (columns 8*tid .. 8*tid+7)
        const float4* bb4 = reinterpret_cast<const float4*>(b_buf + n * P) + tid * 2;
        float4 B0 = __ldcg(bb4);
        float4 B1 = __ldcg(bb4 + 1);

        float c0 = 0.f, c1 = 0.f, c2 = 0.f, c3 = 0.f;
        float c4 = 0.f, c5 = 0.f, c6 = 0.f, c7 = 0.f;

        for (int band = r; band < NBANDS; band += Bb) {
            const uint4* Kb = reinterpret_cast<const uint4*>(
                K2 + (size_t)(n * P + band * RB) * (P / 2));

            uint4 kk[RB];   // raw bf16 pairs, reused by both passes

            // pass 1: row dots with register b, warp shfl-reduce
#pragma unroll
            for (int i = 0; i < RB; i++) {
                kk[i] = Kb[(size_t)i * 256 + tid];
                float s = blo(kk[i].x) * B0.x;
                s = fmaf(bhi(kk[i].x), B0.y, s);
                s = fmaf(blo(kk[i].y), B0.z, s);
                s = fmaf(bhi(kk[i].y), B0.w, s);
                s = fmaf(blo(kk[i].z), B1.x, s);
                s = fmaf(bhi(kk[i].z), B1.y, s);
                s = fmaf(blo(kk[i].w), B1.z, s);
                s = fmaf(bhi(kk[i].w), B1.w, s);
#pragma unroll
                for (int o = 16; o; o >>= 1)
                    s += __shfl_down_sync(0xffffffffu, s, o);
                if (l == 0) wsum[i * 8 + w] = s;
            }
            __syncthreads();

            if (tid < RB) {
                float s = 0.f;
#pragma unroll
                for (int j = 0; j < 8; j++) s += wsum[tid * 8 + j];
                int row = band * RB + tid;
                float av = __fdividef(__ldg(mu + n * P + row) + 1e-8f, s);
                ash[tid] = av;
                if (it == NITER - 1) a_buf[n * P + row] = av;
            }
            __syncthreads();

            // pass 2: column partials, re-expanding the SAME kk registers
            // (ALU-pipe expansion is cheap; saves 32 registers vs caching)
#pragma unroll
            for (int i = 0; i < RB; i++) {
                float ai = ash[i];
                c0 = fmaf(ai, blo(kk[i].x), c0);  c1 = fmaf(ai, bhi(kk[i].x), c1);
                c2 = fmaf(ai, blo(kk[i].y), c2);  c3 = fmaf(ai, bhi(kk[i].y), c3);
                c4 = fmaf(ai, blo(kk[i].z), c4);  c5 = fmaf(ai, bhi(kk[i].z), c5);
                c6 = fmaf(ai, blo(kk[i].w), c6);  c7 = fmaf(ai, bhi(kk[i].w), c7);
            }
            // ash is rewritten only after the next band's first sync, by
            // which time all pass-2 reads are done.
        }

        // publish this block's column partials
        float* wp = partials + (size_t)(n * Bb + r) * P + tid * 8;
        *reinterpret_cast<float4*>(wp)     = make_float4(c0, c1, c2, c3);
        *reinterpret_cast<float4*>(wp + 4) = make_float4(c4, c5, c6, c7);

        batch_sync(n, Bb);

        // distributed b-reduce (batch-local): 4 threads per column entry,
        // 4 independent accumulators for MLP, shfl-combine in 4-lane groups.
        {
            int t = r * TPB + tid;              // 0 .. Bb*256-1
            int e = t >> 2;                     // column entry
            int q = t & 3;                      // lane within 4-group
            float s0 = 0.f, s1 = 0.f, s2 = 0.f, s3 = 0.f;
            if (e < P) {
                const float* pp = partials + (size_t)n * Bb * P + e;
                int k = q;
                for (; k + 12 < Bb; k += 16) {
                    s0 += __ldcg(pp + (size_t)k * P);
                    s1 += __ldcg(pp + (size_t)(k + 4) * P);
                    s2 += __ldcg(pp + (size_t)(k + 8) * P);
                    s3 += __ldcg(pp + (size_t)(k + 12) * P);
                }
                for (; k < Bb; k += 4) s0 += __ldcg(pp + (size_t)k * P);
            }
            float s = (s0 + s1) + (s2 + s3);
            s += __shfl_down_sync(0xffffffffu, s, 1, 4);
            s += __shfl_down_sync(0xffffffffu, s, 2, 4);
            if (e < P && q == 0)
                b_buf[n * P + e] = __fdividef(__ldg(nu + n * P + e) + 1e-8f, s);
        }

        batch_sync(n, Bb);
    }
}

// ---------------------------------------------------------------------------
// pi = exp(ln a + ln b - 10*C) from ORIGINAL fp32 C; cost partials; C copy
__global__ __launch_bounds__(256) void k_epi(const float* __restrict__ C,
                                             float* __restrict__ pi_out,
                                             float* __restrict__ c_out) {
    int n    = blockIdx.y;
    int row0 = blockIdx.x * 16;
    __shared__ float lbsh[P];
    __shared__ float sred[256];
    for (int j = threadIdx.x; j < P; j += 256)
        lbsh[j] = __logf(b_buf[n * P + j]);
    __syncthreads();
    float local = 0.0f;
    for (int r = 0; r < 16; r++) {
        int row = row0 + r;
        float la = __logf(a_buf[n * P + row]);
        size_t base = ((size_t)n * P + row) * P;
        const float4* Cr = reinterpret_cast<const float4*>(C + base);
        float4* Pr = pi_out ? reinterpret_cast<float4*>(pi_out + base) : nullptr;
        float4* Or = c_out  ? reinterpret_cast<float4*>(c_out  + base) : nullptr;
        for (int q = threadIdx.x; q < P / 4; q += 256) {
            float4 c = __ldcs(Cr + q);
            int j = q * 4;
            float4 pi;
            pi.x = __expf(la + lbsh[j]     - INV_EPS * c.x);
            pi.y = __expf(la + lbsh[j + 1] - INV_EPS * c.y);
            pi.z = __expf(la + lbsh[j + 2] - INV_EPS * c.z);
            pi.w = __expf(la + lbsh[j + 3] - INV_EPS * c.w);
            if (Pr) __stcs(Pr + q, pi);
            if (Or) __stcs(Or + q, c);
            local += pi.x * c.x + pi.y * c.y + pi.z * c.z + pi.w * c.w;
        }
    }
    sred[threadIdx.x] = local;
    __syncthreads();
    for (int o = 128; o; o >>= 1) {
        if (threadIdx.x < o) sred[threadIdx.x] += sred[threadIdx.x + o];
        __syncthreads();
    }
    if (threadIdx.x == 0) cost_part[n * 128 + blockIdx.x] = sred[0];
}

__global__ __launch_bounds__(128) void k_cost(float* __restrict__ out) {
    int n = blockIdx.x;
    __shared__ float s[128];
    s[threadIdx.x] = cost_part[n * 128 + threadIdx.x];
    __syncthreads();
    for (int o = 64; o; o >>= 1) {
        if (threadIdx.x < o) s[threadIdx.x] += s[threadIdx.x + o];
        __syncthreads();
    }
    if (threadIdx.x == 0) out[n] = s[0];
}

// ---------------------------------------------------------------------------
extern "C" void kernel_launch(void* const* d_in, const int* in_sizes, int n_in,
                              void* d_out, int out_size) {
    const float* C  = (const float*)d_in[0];
    const float* mu = (const float*)d_in[1];
    const float* nu = (const float*)d_in[2];
    float* out = (float*)d_out;

    const long long PI_ELEMS = (long long)N_B * P * P;  // 33554432
    float* pi_out = nullptr;
    float* c_out  = nullptr;
    if ((long long)out_size >= 8 + PI_ELEMS)     pi_out = out + 8;
    if ((long long)out_size >= 8 + 2 * PI_ELEMS) c_out  = out + 8 + PI_ELEMS;

    static int G = 0, Bb = 0;
    if (G == 0) {   // host-side, deterministic per process
        int dev = 0, nsm = 148, maxb = 1;
        cudaGetDevice(&dev);
        cudaDeviceGetAttribute(&nsm, cudaDevAttrMultiProcessorCount, dev);
        cudaOccupancyMaxActiveBlocksPerMultiprocessor(&maxb, k_main, TPB, 0);
        if (maxb < 1) maxb = 1;
        long long tot = (long long)nsm * maxb;
        Bb = (int)(tot / N_B);
        if (Bb > MAXBB) Bb = MAXBB;
        if (Bb < 32) Bb = 32;   // b-reduce needs Bb*256 >= 4*P threads
        G = Bb * N_B;
    }

    k_prep<<<32768, 256>>>(C);
    k_main<<<G, TPB>>>(mu, nu, Bb);
    k_epi<<<dim3(128, N_B), 256>>>(C, pi_out, c_out);
    k_cost<<<N_B, 128>>>(out);
}